// round 3
// baseline (speedup 1.0000x reference)
#include <cuda_runtime.h>
#include <cuda_bf16.h>
#include <cstdint>

#define NN 20000
#define NE 320000
#define HID 256
#define NHEADS 8
#define HD 32

// ---------------- scratch (static device globals; no allocation) -------------
__device__ float g_q[(size_t)NN * HID];
__device__ float g_k[(size_t)NN * HID];
__device__ float g_v[(size_t)NN * HID];
__device__ float g_o[(size_t)NN * HID];
__device__ float g_s[(size_t)NE * NHEADS];
__device__ int   g_deg[NN];
__device__ int   g_off[NN + 1];
__device__ int   g_fill[NN];
__device__ int   g_perm[NE];

// ---------------- GEMM: C[M,256] = (A[M,256] @ W[256,256] + bias) * scale ----
__global__ __launch_bounds__(256) void gemm256(
    const float* __restrict__ A, const float* __restrict__ W,
    const float* __restrict__ bias, float* __restrict__ C,
    int M, float scale)
{
    __shared__ float As[16][68];   // [k][row], padded
    __shared__ float Bs[16][64];   // [k][col]

    int tid = threadIdx.x;
    int tx = tid & 15, ty = tid >> 4;
    int rowBase = blockIdx.y * 64;
    int colBase = blockIdx.x * 64;

    int arow  = tid >> 2;          // 0..63
    int ak4   = (tid & 3) << 2;    // 0,4,8,12
    int brow  = tid >> 4;          // 0..15
    int bcol4 = (tid & 15) << 2;   // 0..60

    float acc[4][4];
    #pragma unroll
    for (int i = 0; i < 4; i++)
        #pragma unroll
        for (int j = 0; j < 4; j++) acc[i][j] = 0.f;

    for (int kb = 0; kb < 256; kb += 16) {
        float4 av = make_float4(0.f, 0.f, 0.f, 0.f);
        if (rowBase + arow < M)
            av = *(const float4*)(A + (size_t)(rowBase + arow) * 256 + kb + ak4);
        As[ak4 + 0][arow] = av.x;
        As[ak4 + 1][arow] = av.y;
        As[ak4 + 2][arow] = av.z;
        As[ak4 + 3][arow] = av.w;
        *(float4*)&Bs[brow][bcol4] =
            *(const float4*)(W + (size_t)(kb + brow) * 256 + colBase + bcol4);
        __syncthreads();

        #pragma unroll
        for (int kk = 0; kk < 16; kk++) {
            float4 a = *(const float4*)&As[kk][ty << 2];
            float4 b = *(const float4*)&Bs[kk][tx << 2];
            float ar[4] = {a.x, a.y, a.z, a.w};
            float br[4] = {b.x, b.y, b.z, b.w};
            #pragma unroll
            for (int i = 0; i < 4; i++)
                #pragma unroll
                for (int j = 0; j < 4; j++)
                    acc[i][j] += ar[i] * br[j];
        }
        __syncthreads();
    }

    #pragma unroll
    for (int i = 0; i < 4; i++) {
        int r = rowBase + (ty << 2) + i;
        if (r < M) {
            int c0 = colBase + (tx << 2);
            float4 bv = *(const float4*)(bias + c0);
            float4 o;
            o.x = (acc[i][0] + bv.x) * scale;
            o.y = (acc[i][1] + bv.y) * scale;
            o.z = (acc[i][2] + bv.z) * scale;
            o.w = (acc[i][3] + bv.w) * scale;
            *(float4*)(C + (size_t)r * 256 + c0) = o;
        }
    }
}

// ---------------- CSR build ---------------------------------------------------
__global__ void zero_counts() {
    int i = blockIdx.x * blockDim.x + threadIdx.x;
    if (i < NN) { g_deg[i] = 0; g_fill[i] = 0; }
}

__global__ void count_deg(const int* __restrict__ rows) {
    int i = blockIdx.x * blockDim.x + threadIdx.x;
    if (i < NE) atomicAdd(&g_deg[rows[i]], 1);
}

__global__ __launch_bounds__(1024) void scan_deg() {
    __shared__ int warp_sums[32];
    __shared__ int carry;
    int tid = threadIdx.x;
    int lane = tid & 31, w = tid >> 5;
    if (tid == 0) carry = 0;
    __syncthreads();
    for (int base = 0; base < NN; base += 1024) {
        int i = base + tid;
        int v = (i < NN) ? g_deg[i] : 0;
        int x = v;
        #pragma unroll
        for (int d = 1; d < 32; d <<= 1) {
            int y = __shfl_up_sync(0xffffffffu, x, d);
            if (lane >= d) x += y;
        }
        if (lane == 31) warp_sums[w] = x;
        __syncthreads();
        if (w == 0) {
            int s = warp_sums[lane];
            #pragma unroll
            for (int d = 1; d < 32; d <<= 1) {
                int y = __shfl_up_sync(0xffffffffu, s, d);
                if (lane >= d) s += y;
            }
            warp_sums[lane] = s;
        }
        __syncthreads();
        int excl = x - v + carry + (w ? warp_sums[w - 1] : 0);
        if (i < NN) g_off[i] = excl;
        int blocktotal = warp_sums[31];
        __syncthreads();
        if (tid == 0) carry += blocktotal;
        __syncthreads();
    }
    if (tid == 0) g_off[NN] = carry;
}

__global__ void scatter_edges(const int* __restrict__ rows) {
    int i = blockIdx.x * blockDim.x + threadIdx.x;
    if (i < NE) {
        int r = rows[i];
        int pos = g_off[r] + atomicAdd(&g_fill[r], 1);
        g_perm[pos] = i;
    }
}

// deterministic per-row order (atomics above are order-racy)
__global__ void sort_perm() {
    int r = blockIdx.x * blockDim.x + threadIdx.x;
    if (r >= NN) return;
    int b = g_off[r], e = g_off[r + 1];
    for (int i = b + 1; i < e; i++) {
        int key = g_perm[i];
        int j = i - 1;
        while (j >= b && g_perm[j] > key) { g_perm[j + 1] = g_perm[j]; j--; }
        g_perm[j + 1] = key;
    }
}

// ---------------- SDDMM: s[e,h] = sum_{c%8==h} q[r][c]*k[c'][c] ---------------
__global__ __launch_bounds__(256) void sddmm(
    const int* __restrict__ rows, const int* __restrict__ cols)
{
    int wid = (blockIdx.x * blockDim.x + threadIdx.x) >> 5;
    if (wid >= NE) return;
    int lane = threadIdx.x & 31;
    int r = __ldg(&rows[wid]);
    int c = __ldg(&cols[wid]);
    const float4* q4 = reinterpret_cast<const float4*>(g_q + (size_t)r * 256);
    const float4* k4 = reinterpret_cast<const float4*>(g_k + (size_t)c * 256);
    float4 qa = q4[lane], qb = q4[lane + 32];
    float4 ka = k4[lane], kb = k4[lane + 32];
    float4 acc;
    acc.x = qa.x * ka.x + qb.x * kb.x;
    acc.y = qa.y * ka.y + qb.y * kb.y;
    acc.z = qa.z * ka.z + qb.z * kb.z;
    acc.w = qa.w * ka.w + qb.w * kb.w;
    // heads: even lanes carry heads 0..3, odd lanes heads 4..7 (c%8 layout)
    #pragma unroll
    for (int m = 2; m <= 16; m <<= 1) {
        acc.x += __shfl_xor_sync(0xffffffffu, acc.x, m);
        acc.y += __shfl_xor_sync(0xffffffffu, acc.y, m);
        acc.z += __shfl_xor_sync(0xffffffffu, acc.z, m);
        acc.w += __shfl_xor_sync(0xffffffffu, acc.w, m);
    }
    if (lane < 2)
        *(float4*)(g_s + (size_t)wid * 8 + lane * 4) = acc;
}

// ------------- per-row softmax + SPMM (one warp per row) ---------------------
__global__ __launch_bounds__(256) void softmax_spmm(const int* __restrict__ cols)
{
    int row = (blockIdx.x * blockDim.x + threadIdx.x) >> 5;
    if (row >= NN) return;
    int lane = threadIdx.x & 31;
    int beg = g_off[row], end = g_off[row + 1];

    float m = -1e30f, z = 0.f;
    if (lane < 8) {
        for (int t = beg; t < end; t++) {
            float s = g_s[(size_t)g_perm[t] * 8 + lane];
            m = fmaxf(m, s);
        }
        for (int t = beg; t < end; t++) {
            float s = g_s[(size_t)g_perm[t] * 8 + lane];
            z += __expf(s - m);
        }
    }
    float mh = __shfl_sync(0xffffffffu, m, lane & 7);
    float zh = __shfl_sync(0xffffffffu, z, lane & 7);
    float inv_z = (end > beg) ? (1.f / zh) : 0.f;

    float acc[8];
    #pragma unroll
    for (int j = 0; j < 8; j++) acc[j] = 0.f;

    for (int t = beg; t < end; t++) {
        int e = g_perm[t];
        int c = __ldg(&cols[e]);
        float p = __expf(g_s[(size_t)e * 8 + (lane & 7)] - mh) * inv_z;
        const float* vr = g_v + (size_t)c * 256;
        #pragma unroll
        for (int j = 0; j < 8; j++)
            acc[j] += p * vr[lane + 32 * j];
    }
    float* orow = g_o + (size_t)row * 256;
    #pragma unroll
    for (int j = 0; j < 8; j++)
        orow[lane + 32 * j] = acc[j];
}

// ---------------- launch -----------------------------------------------------
extern "C" void kernel_launch(void* const* d_in, const int* in_sizes, int n_in,
                              void* d_out, int out_size)
{
    const float* h  = (const float*)d_in[0];
    const float* Wq = (const float*)d_in[1];
    const float* bq = (const float*)d_in[2];
    const float* Wk = (const float*)d_in[3];
    const float* bk = (const float*)d_in[4];
    const float* Wv = (const float*)d_in[5];
    const float* bv = (const float*)d_in[6];
    const float* Wo = (const float*)d_in[7];
    const float* bo = (const float*)d_in[8];
    const int* rows = (const int*)d_in[9];
    const int* cols = (const int*)d_in[10];
    float* out = (float*)d_out;

    void *pq, *pk, *pv, *po;
    cudaGetSymbolAddress(&pq, g_q);
    cudaGetSymbolAddress(&pk, g_k);
    cudaGetSymbolAddress(&pv, g_v);
    cudaGetSymbolAddress(&po, g_o);

    const float scaling = 0.17677669529663687f;  // 32^-0.5

    dim3 gB(256 / 64, (NN + 63) / 64);  // (4, 313)
    gemm256<<<gB, 256>>>(h, Wq, bq, (float*)pq, NN, scaling);
    gemm256<<<gB, 256>>>(h, Wk, bk, (float*)pk, NN, 1.f);
    gemm256<<<gB, 256>>>(h, Wv, bv, (float*)pv, NN, 1.f);

    zero_counts<<<(NN + 255) / 256, 256>>>();
    count_deg<<<(NE + 255) / 256, 256>>>(rows);
    scan_deg<<<1, 1024>>>();
    scatter_edges<<<(NE + 255) / 256, 256>>>(rows);
    sort_perm<<<(NN + 255) / 256, 256>>>();

    sddmm<<<(NE * 32 + 255) / 256, 256>>>(rows, cols);
    softmax_spmm<<<(NN * 32 + 255) / 256, 256>>>(cols);

    gemm256<<<gB, 256>>>((const float*)po, Wo, bo, out, NN, 1.f);
}

// round 8
// speedup vs baseline: 1.6636x; 1.6636x over previous
#include <cuda_runtime.h>
#include <cuda_bf16.h>
#include <cstdint>

#define NN 20000
#define NE 320000
#define HID 256
#define NHEADS 8
#define MB_TOT 1256          // ceil(157*128/16) row-blocks of 16 (padded)

// ---------------- scratch (static device globals; no allocation) -------------
__device__ float g_af[(size_t)MB_TOT * 32 * 128];  // A fragments (tf32 h)
__device__ float g_of[(size_t)MB_TOT * 32 * 128];  // attention-out fragments
__device__ float g_wf[4][32 * 32 * 64];            // weight fragments (Wq,Wk,Wv,Wo)
__device__ float g_q [(size_t)NN * HID];
__device__ float g_k [(size_t)NN * HID];
__device__ float g_v [(size_t)NN * HID];
__device__ float g_s [(size_t)NE * NHEADS];
__device__ int   g_deg[NN];
__device__ int   g_off[NN + 1];
__device__ int   g_fill[NN];
__device__ int   g_perm[NE];

// ---------------- helpers ----------------------------------------------------
__device__ __forceinline__ uint32_t smem_u32(const void* p) {
    uint32_t a;
    asm("{ .reg .u64 t; cvta.to.shared.u64 t, %1; cvt.u32.u64 %0, t; }" : "=r"(a) : "l"(p));
    return a;
}
__device__ __forceinline__ float f2tf32(float a) {
    uint32_t u; asm("cvt.rna.tf32.f32 %0, %1;" : "=r"(u) : "f"(a));
    return __uint_as_float(u);
}
// fragment-ready A layout: per 16x8 tile, lane = (row%8)*4 + (col%4),
// regs a0..a3 = (row+8?, col+4?) quadrants, tiles [mb][kb] contiguous (128 floats)
__device__ __forceinline__ size_t frag_a_idx(int row, int c) {
    return ((size_t)(row >> 4) * 32 + (c >> 3)) * 128 +
           ((row & 7) * 4 + (c & 3)) * 4 + ((row >> 3) & 1) + 2 * ((c >> 2) & 1);
}
// fragment-ready B layout (from W[k][n]): per 8n x 8k tile, lane = (n%8)*4+(k%4),
// regs b0,b1 = k / k+4; tiles [nb][kb] contiguous (64 floats)
__device__ __forceinline__ size_t frag_b_idx(int k, int n) {
    return ((size_t)(n >> 3) * 32 + (k >> 3)) * 64 +
           ((n & 7) * 4 + (k & 3)) * 2 + ((k >> 2) & 1);
}
__device__ __forceinline__ void cp_async16(uint32_t dst, const float* src) {
    asm volatile("cp.async.cg.shared.global [%0], [%1], 16;" :: "r"(dst), "l"(src) : "memory");
}
__device__ __forceinline__ void mma1688(float* d, const float4& a, const float2& b) {
    asm volatile(
        "mma.sync.aligned.m16n8k8.row.col.f32.tf32.tf32.f32 "
        "{%0,%1,%2,%3}, {%4,%5,%6,%7}, {%8,%9}, {%0,%1,%2,%3};"
        : "+f"(d[0]), "+f"(d[1]), "+f"(d[2]), "+f"(d[3])
        : "r"(__float_as_uint(a.x)), "r"(__float_as_uint(a.y)),
          "r"(__float_as_uint(a.z)), "r"(__float_as_uint(a.w)),
          "r"(__float_as_uint(b.x)), "r"(__float_as_uint(b.y)));
}

// ---------------- prep: tf32 round + fragment swizzle ------------------------
__global__ void prep_a(const float* __restrict__ h) {
    int i = blockIdx.x * blockDim.x + threadIdx.x;
    if (i >= NN * HID) return;
    int row = i >> 8, c = i & 255;
    g_af[frag_a_idx(row, c)] = f2tf32(h[i]);
}
__global__ void prep_w(const float* __restrict__ W, float* __restrict__ dst) {
    int i = blockIdx.x * blockDim.x + threadIdx.x;
    if (i >= HID * HID) return;
    int k = i >> 8, n = i & 255;
    dst[frag_b_idx(k, n)] = f2tf32(W[i]);
}

// ---------------- tf32 mma.sync GEMM: C = (A @ W + bias) * scale -------------
// CTA 128(M) x 128(N), 8 warps (2x4), warp tile 64x32, K-chunk 32, 2 stages.
#define SMEM_GEMM 65536

__device__ __forceinline__ void load_stage(
    uint32_t da, uint32_t db, int c, const float* __restrict__ Af,
    const float* __restrict__ Bf, int mb0, int nb0, int tid)
{
    #pragma unroll
    for (int i = 0; i < 4; i++) {      // A: 1024 x 16B
        int idx = tid + i * 256;
        int mbL = idx >> 7, kbL = (idx >> 5) & 3, l = idx & 31;
        const float* src = Af + ((size_t)(mb0 + mbL) * 32 + c * 4 + kbL) * 128 + l * 4;
        cp_async16(da + idx * 16, src);
    }
    #pragma unroll
    for (int i = 0; i < 4; i++) {      // B: 1024 x 16B
        int idx = tid + i * 256;
        int nbL = idx >> 6, kbL = (idx >> 4) & 3, part = idx & 15;
        const float* src = Bf + ((size_t)(nb0 + nbL) * 32 + c * 4 + kbL) * 64 + part * 4;
        cp_async16(db + idx * 16, src);
    }
    asm volatile("cp.async.commit_group;" ::: "memory");
}

__global__ void __launch_bounds__(256) gemm_mma(
    const float* __restrict__ Af, const float* __restrict__ Bf,
    const float* __restrict__ bias, float* __restrict__ C, int M, float scale)
{
    extern __shared__ float sm[];
    float* sA[2] = { sm,        sm + 4096 };
    float* sB[2] = { sm + 8192, sm + 12288 };
    uint32_t uA[2] = { smem_u32(sA[0]), smem_u32(sA[1]) };
    uint32_t uB[2] = { smem_u32(sB[0]), smem_u32(sB[1]) };

    int tid = threadIdx.x, wid = tid >> 5, lane = tid & 31;
    int wm = wid >> 2, wn = wid & 3;
    int mb0 = blockIdx.x * 8;
    int nb0 = blockIdx.y * 16;

    float acc[4][4][4];
    #pragma unroll
    for (int a = 0; a < 4; a++)
        #pragma unroll
        for (int b = 0; b < 4; b++)
            #pragma unroll
            for (int r = 0; r < 4; r++) acc[a][b][r] = 0.f;

    load_stage(uA[0], uB[0], 0, Af, Bf, mb0, nb0, tid);

    #pragma unroll
    for (int c = 0; c < 8; c++) {
        if (c < 7) {
            load_stage(uA[(c + 1) & 1], uB[(c + 1) & 1], c + 1, Af, Bf, mb0, nb0, tid);
            asm volatile("cp.async.wait_group 1;" ::: "memory");
        } else {
            asm volatile("cp.async.wait_group 0;" ::: "memory");
        }
        __syncthreads();
        const float* cA = sA[c & 1];
        const float* cB = sB[c & 1];
        #pragma unroll
        for (int s = 0; s < 4; s++) {
            float4 a[4];
            float2 b[4];
            #pragma unroll
            for (int mi = 0; mi < 4; mi++)
                a[mi] = *(const float4*)(cA + ((wm * 4 + mi) * 4 + s) * 128 + lane * 4);
            #pragma unroll
            for (int ni = 0; ni < 4; ni++)
                b[ni] = *(const float2*)(cB + ((wn * 4 + ni) * 4 + s) * 64 + lane * 2);
            #pragma unroll
            for (int mi = 0; mi < 4; mi++)
                #pragma unroll
                for (int ni = 0; ni < 4; ni++)
                    mma1688(acc[mi][ni], a[mi], b[ni]);
        }
        __syncthreads();
    }

    // epilogue
    int rbase = blockIdx.x * 128 + wm * 64 + (lane >> 2);
    int cbase = nb0 * 8 + wn * 32 + (lane & 3) * 2;
    #pragma unroll
    for (int mi = 0; mi < 4; mi++) {
        #pragma unroll
        for (int half = 0; half < 2; half++) {
            int row = rbase + mi * 16 + half * 8;
            if (row < M) {
                #pragma unroll
                for (int ni = 0; ni < 4; ni++) {
                    int col = cbase + ni * 8;
                    float2 o;
                    o.x = (acc[mi][ni][half * 2 + 0] + bias[col])     * scale;
                    o.y = (acc[mi][ni][half * 2 + 1] + bias[col + 1]) * scale;
                    *(float2*)(C + (size_t)row * 256 + col) = o;
                }
            }
        }
    }
}

// ---------------- CSR build ---------------------------------------------------
__global__ void zero_counts() {
    int i = blockIdx.x * blockDim.x + threadIdx.x;
    if (i < NN) { g_deg[i] = 0; g_fill[i] = 0; }
}
__global__ void count_deg(const int* __restrict__ rows) {
    int i = blockIdx.x * blockDim.x + threadIdx.x;
    if (i < NE) atomicAdd(&g_deg[rows[i]], 1);
}
__global__ __launch_bounds__(1024) void scan_deg() {
    __shared__ int warp_sums[32];
    __shared__ int carry;
    int tid = threadIdx.x;
    int lane = tid & 31, w = tid >> 5;
    if (tid == 0) carry = 0;
    __syncthreads();
    for (int base = 0; base < NN; base += 1024) {
        int i = base + tid;
        int v = (i < NN) ? g_deg[i] : 0;
        int x = v;
        #pragma unroll
        for (int d = 1; d < 32; d <<= 1) {
            int y = __shfl_up_sync(0xffffffffu, x, d);
            if (lane >= d) x += y;
        }
        if (lane == 31) warp_sums[w] = x;
        __syncthreads();
        if (w == 0) {
            int s = warp_sums[lane];
            #pragma unroll
            for (int d = 1; d < 32; d <<= 1) {
                int y = __shfl_up_sync(0xffffffffu, s, d);
                if (lane >= d) s += y;
            }
            warp_sums[lane] = s;
        }
        __syncthreads();
        int excl = x - v + carry + (w ? warp_sums[w - 1] : 0);
        if (i < NN) g_off[i] = excl;
        int blocktotal = warp_sums[31];
        __syncthreads();
        if (tid == 0) carry += blocktotal;
        __syncthreads();
    }
    if (tid == 0) g_off[NN] = carry;
}
__global__ void scatter_edges(const int* __restrict__ rows) {
    int i = blockIdx.x * blockDim.x + threadIdx.x;
    if (i < NE) {
        int r = rows[i];
        int pos = g_off[r] + atomicAdd(&g_fill[r], 1);
        g_perm[pos] = i;
    }
}
__global__ void sort_perm() {
    int r = blockIdx.x * blockDim.x + threadIdx.x;
    if (r >= NN) return;
    int b = g_off[r], e = g_off[r + 1];
    for (int i = b + 1; i < e; i++) {
        int key = g_perm[i];
        int j = i - 1;
        while (j >= b && g_perm[j] > key) { g_perm[j + 1] = g_perm[j]; j--; }
        g_perm[j + 1] = key;
    }
}

// ------- SDDMM in perm order (consecutive warps share q row -> L1 hit) -------
__global__ __launch_bounds__(256) void sddmm(
    const int* __restrict__ rows, const int* __restrict__ cols)
{
    int t = (blockIdx.x * blockDim.x + threadIdx.x) >> 5;
    if (t >= NE) return;
    int lane = threadIdx.x & 31;
    int e = g_perm[t];
    int r = __ldg(&rows[e]);
    int c = __ldg(&cols[e]);
    const float4* q4 = reinterpret_cast<const float4*>(g_q + (size_t)r * 256);
    const float4* k4 = reinterpret_cast<const float4*>(g_k + (size_t)c * 256);
    float4 qa = q4[lane], qb = q4[lane + 32];
    float4 ka = k4[lane], kb = k4[lane + 32];
    float4 acc;
    acc.x = qa.x * ka.x + qb.x * kb.x;
    acc.y = qa.y * ka.y + qb.y * kb.y;
    acc.z = qa.z * ka.z + qb.z * kb.z;
    acc.w = qa.w * ka.w + qb.w * kb.w;
    #pragma unroll
    for (int m = 2; m <= 16; m <<= 1) {
        acc.x += __shfl_xor_sync(0xffffffffu, acc.x, m);
        acc.y += __shfl_xor_sync(0xffffffffu, acc.y, m);
        acc.z += __shfl_xor_sync(0xffffffffu, acc.z, m);
        acc.w += __shfl_xor_sync(0xffffffffu, acc.w, m);
    }
    if (lane < 2)
        *(float4*)(g_s + (size_t)e * 8 + lane * 4) = acc;
}

// --- per-row softmax + SPMM (warp/row); writes tf32-rounded FRAGMENT layout --
__global__ __launch_bounds__(256) void softmax_spmm(const int* __restrict__ cols)
{
    int row = (blockIdx.x * blockDim.x + threadIdx.x) >> 5;
    if (row >= NN) return;
    int lane = threadIdx.x & 31;
    int beg = g_off[row], end = g_off[row + 1];
    int sub = lane >> 3;       // 4-way edge parallelism
    int hh  = lane & 7;        // head

    float m = -1e30f;
    for (int t = beg + sub; t < end; t += 4)
        m = fmaxf(m, g_s[(size_t)g_perm[t] * 8 + hh]);
    m = fmaxf(m, __shfl_xor_sync(0xffffffffu, m, 8));
    m = fmaxf(m, __shfl_xor_sync(0xffffffffu, m, 16));

    float z = 0.f;
    for (int t = beg + sub; t < end; t += 4)
        z += __expf(g_s[(size_t)g_perm[t] * 8 + hh] - m);
    z += __shfl_xor_sync(0xffffffffu, z, 8);
    z += __shfl_xor_sync(0xffffffffu, z, 16);
    float inv_z = (end > beg) ? (1.f / z) : 0.f;

    float acc[8];
    #pragma unroll
    for (int j = 0; j < 8; j++) acc[j] = 0.f;

    for (int t = beg; t < end; t++) {
        int e = g_perm[t];
        int c = __ldg(&cols[e]);
        float p = __expf(g_s[(size_t)e * 8 + hh] - m) * inv_z;
        const float* vr = g_v + (size_t)c * 256;
        #pragma unroll
        for (int j = 0; j < 8; j++)
            acc[j] += p * vr[lane + 32 * j];
    }
    #pragma unroll
    for (int j = 0; j < 8; j++) {
        int c = lane + 32 * j;
        g_of[frag_a_idx(row, c)] = f2tf32(acc[j]);
    }
}

// ---------------- launch -----------------------------------------------------
extern "C" void kernel_launch(void* const* d_in, const int* in_sizes, int n_in,
                              void* d_out, int out_size)
{
    const float* h  = (const float*)d_in[0];
    const float* Wq = (const float*)d_in[1];
    const float* bq = (const float*)d_in[2];
    const float* Wk = (const float*)d_in[3];
    const float* bk = (const float*)d_in[4];
    const float* Wv = (const float*)d_in[5];
    const float* bv = (const float*)d_in[6];
    const float* Wo = (const float*)d_in[7];
    const float* bo = (const float*)d_in[8];
    const int* rows = (const int*)d_in[9];
    const int* cols = (const int*)d_in[10];
    float* out = (float*)d_out;

    void *paf, *pof, *pwf, *pq, *pk, *pv;
    cudaGetSymbolAddress(&paf, g_af);
    cudaGetSymbolAddress(&pof, g_of);
    cudaGetSymbolAddress(&pwf, g_wf);
    cudaGetSymbolAddress(&pq, g_q);
    cudaGetSymbolAddress(&pk, g_k);
    cudaGetSymbolAddress(&pv, g_v);
    float* wf = (float*)pwf;

    cudaFuncSetAttribute(gemm_mma, cudaFuncAttributeMaxDynamicSharedMemorySize, SMEM_GEMM);

    const float scaling = 0.17677669529663687f;  // 32^-0.5

    // prep: tf32 round + fragment swizzle
    prep_a<<<(NN * HID + 255) / 256, 256>>>(h);
    prep_w<<<(HID * HID + 255) / 256, 256>>>(Wq, wf + 0 * 32 * 32 * 64);
    prep_w<<<(HID * HID + 255) / 256, 256>>>(Wk, wf + 1 * 32 * 32 * 64);
    prep_w<<<(HID * HID + 255) / 256, 256>>>(Wv, wf + 2 * 32 * 32 * 64);
    prep_w<<<(HID * HID + 255) / 256, 256>>>(Wo, wf + 3 * 32 * 32 * 64);

    dim3 gG((NN + 127) / 128, 2);  // (157, 2)
    gemm_mma<<<gG, 256, SMEM_GEMM>>>((const float*)paf, wf + 0 * 32 * 32 * 64, bq, (float*)pq, NN, scaling);
    gemm_mma<<<gG, 256, SMEM_GEMM>>>((const float*)paf, wf + 1 * 32 * 32 * 64, bk, (float*)pk, NN, 1.f);
    gemm_mma<<<gG, 256, SMEM_GEMM>>>((const float*)paf, wf + 2 * 32 * 32 * 64, bv, (float*)pv, NN, 1.f);

    zero_counts<<<(NN + 255) / 256, 256>>>();
    count_deg<<<(NE + 255) / 256, 256>>>(rows);
    scan_deg<<<1, 1024>>>();
    scatter_edges<<<(NE + 255) / 256, 256>>>(rows);
    sort_perm<<<(NN + 255) / 256, 256>>>();

    sddmm<<<(NE * 32 + 255) / 256, 256>>>(rows, cols);
    softmax_spmm<<<(NN * 32 + 255) / 256, 256>>>(cols);

    gemm_mma<<<gG, 256, SMEM_GEMM>>>((const float*)pof, wf + 3 * 32 * 32 * 64, bo, out, NN, 1.f);
}

// round 11
// speedup vs baseline: 1.7707x; 1.0644x over previous
#include <cuda_runtime.h>
#include <cuda_bf16.h>
#include <cstdint>

#define NN 20000
#define NE 320000
#define HID 256
#define NQKV 768
#define NHEADS 8
#define MB_TOT 1256          // 157*8 row-blocks of 16 (padded)

// ---------------- scratch (static device globals; no allocation) -------------
__device__ float g_af [(size_t)MB_TOT * 32 * 128];  // A fragments (tf32 h)
__device__ float g_of [(size_t)MB_TOT * 32 * 128];  // attention-out fragments
__device__ float g_wf [262144];                     // Wqkv frags [196608] + Wo frags [65536]
__device__ float g_bias[NQKV];                      // concat bq|bk|bv
__device__ float g_qkv[(size_t)NN * NQKV];          // q|k|v rows
__device__ float g_s  [(size_t)NE * NHEADS];
__device__ int   g_deg[NN];
__device__ int   g_off[NN + 1];
__device__ int   g_fill[NN];
__device__ int   g_perm[NE];

// ---------------- helpers ----------------------------------------------------
__device__ __forceinline__ uint32_t smem_u32(const void* p) {
    uint32_t a;
    asm("{ .reg .u64 t; cvta.to.shared.u64 t, %1; cvt.u32.u64 %0, t; }" : "=r"(a) : "l"(p));
    return a;
}
__device__ __forceinline__ float f2tf32(float a) {
    uint32_t u; asm("cvt.rna.tf32.f32 %0, %1;" : "=r"(u) : "f"(a));
    return __uint_as_float(u);
}
// fragment-ready A layout: per 16x8 tile, lane = (row%8)*4 + (col%4),
// regs a0..a3 = (row+8?, col+4?) quadrants; tiles [mb][kb] contiguous (128 floats)
__device__ __forceinline__ size_t frag_a_idx(int row, int c) {
    return ((size_t)(row >> 4) * 32 + (c >> 3)) * 128 +
           ((row & 7) * 4 + (c & 3)) * 4 + ((row >> 3) & 1) + 2 * ((c >> 2) & 1);
}
// fragment-ready B layout (from W[k][n]): per 8n x 8k tile, lane=(n%8)*4+(k%4),
// regs b0,b1 = k / k+4; tiles [nb][kb] contiguous (64 floats)
__device__ __forceinline__ size_t frag_b_idx(int k, int n) {
    return ((size_t)(n >> 3) * 32 + (k >> 3)) * 64 +
           ((n & 7) * 4 + (k & 3)) * 2 + ((k >> 2) & 1);
}
__device__ __forceinline__ void cp_async16(uint32_t dst, const float* src) {
    asm volatile("cp.async.cg.shared.global [%0], [%1], 16;" :: "r"(dst), "l"(src) : "memory");
}
__device__ __forceinline__ void mma1688(float* d, const float4& a, const float2& b) {
    asm volatile(
        "mma.sync.aligned.m16n8k8.row.col.f32.tf32.tf32.f32 "
        "{%0,%1,%2,%3}, {%4,%5,%6,%7}, {%8,%9}, {%0,%1,%2,%3};"
        : "+f"(d[0]), "+f"(d[1]), "+f"(d[2]), "+f"(d[3])
        : "r"(__float_as_uint(a.x)), "r"(__float_as_uint(a.y)),
          "r"(__float_as_uint(a.z)), "r"(__float_as_uint(a.w)),
          "r"(__float_as_uint(b.x)), "r"(__float_as_uint(b.y)));
}

// ---------------- prep: tf32 round + fragment swizzle ------------------------
__global__ void prep_a(const float* __restrict__ h) {
    int i = blockIdx.x * blockDim.x + threadIdx.x;
    if (i >= NN * HID) return;
    int row = i >> 8, c = i & 255;
    g_af[frag_a_idx(row, c)] = f2tf32(h[i]);
}
// all three QKV weights -> one frag buffer with 768-wide N; plus concat bias
__global__ void prep_wqkv(const float* __restrict__ Wq, const float* __restrict__ Wk,
                          const float* __restrict__ Wv, const float* __restrict__ bq,
                          const float* __restrict__ bk, const float* __restrict__ bv) {
    int i = blockIdx.x * blockDim.x + threadIdx.x;
    if (i < NQKV)
        g_bias[i] = (i < 256) ? bq[i] : (i < 512) ? bk[i - 256] : bv[i - 512];
    if (i >= 3 * HID * HID) return;
    int which = i >> 16, rem = i & 65535;
    int k = rem >> 8, n = rem & 255;
    const float* W = (which == 0) ? Wq : (which == 1) ? Wk : Wv;
    g_wf[frag_b_idx(k, which * 256 + n)] = f2tf32(W[rem]);
}
__global__ void prep_wo(const float* __restrict__ Wo) {
    int i = blockIdx.x * blockDim.x + threadIdx.x;
    if (i >= HID * HID) return;
    int k = i >> 8, n = i & 255;
    g_wf[196608 + frag_b_idx(k, n)] = f2tf32(Wo[i]);
}

// ---------------- tf32 mma.sync GEMM: C = (A @ W + bias) * colscale ----------
// CTA 128(M) x 256(N), 8 warps (2x4), warp tile 64x64, K-chunk 32, 2 stages.
#define SMEM_GEMM 98304

__device__ __forceinline__ void load_stage(
    uint32_t da, uint32_t db, int c, const float* __restrict__ Af,
    const float* __restrict__ Bf, int mb0, int nb0, int tid)
{
    #pragma unroll
    for (int i = 0; i < 4; i++) {      // A: 1024 x 16B
        int idx = tid + i * 256;
        int mbL = idx >> 7, kbL = (idx >> 5) & 3, l = idx & 31;
        const float* src = Af + ((size_t)(mb0 + mbL) * 32 + c * 4 + kbL) * 128 + l * 4;
        cp_async16(da + idx * 16, src);
    }
    #pragma unroll
    for (int i = 0; i < 8; i++) {      // B: 2048 x 16B
        int idx = tid + i * 256;
        int nbL = idx >> 6, kbL = (idx >> 4) & 3, part = idx & 15;
        const float* src = Bf + ((size_t)(nb0 + nbL) * 32 + c * 4 + kbL) * 64 + part * 4;
        cp_async16(db + idx * 16, src);
    }
    asm volatile("cp.async.commit_group;" ::: "memory");
}

__global__ void __launch_bounds__(256) gemm_mma(
    const float* __restrict__ Af, const float* __restrict__ Bf,
    const float* __restrict__ bias, float* __restrict__ C, int M, int ldc,
    float scale, int scale_cols)
{
    extern __shared__ float sm[];
    float* sA[2] = { sm,         sm + 4096 };
    float* sB[2] = { sm + 8192,  sm + 16384 };

    int tid = threadIdx.x, wid = tid >> 5, lane = tid & 31;
    int wm = wid >> 2, wn = wid & 3;
    int mb0 = blockIdx.x * 8;
    int nb0 = blockIdx.y * 32;

    float acc[4][8][4];
    #pragma unroll
    for (int a = 0; a < 4; a++)
        #pragma unroll
        for (int b = 0; b < 8; b++)
            #pragma unroll
            for (int r = 0; r < 4; r++) acc[a][b][r] = 0.f;

    uint32_t uA[2] = { smem_u32(sA[0]), smem_u32(sA[1]) };
    uint32_t uB[2] = { smem_u32(sB[0]), smem_u32(sB[1]) };

    load_stage(uA[0], uB[0], 0, Af, Bf, mb0, nb0, tid);

    #pragma unroll
    for (int c = 0; c < 8; c++) {
        if (c < 7) {
            load_stage(uA[(c + 1) & 1], uB[(c + 1) & 1], c + 1, Af, Bf, mb0, nb0, tid);
            asm volatile("cp.async.wait_group 1;" ::: "memory");
        } else {
            asm volatile("cp.async.wait_group 0;" ::: "memory");
        }
        __syncthreads();
        const float* cA = sA[c & 1];
        const float* cB = sB[c & 1];
        #pragma unroll
        for (int s = 0; s < 4; s++) {
            float4 a[4];
            float2 b[8];
            #pragma unroll
            for (int mi = 0; mi < 4; mi++)
                a[mi] = *(const float4*)(cA + ((wm * 4 + mi) * 4 + s) * 128 + lane * 4);
            #pragma unroll
            for (int ni = 0; ni < 8; ni++)
                b[ni] = *(const float2*)(cB + ((wn * 8 + ni) * 4 + s) * 64 + lane * 2);
            #pragma unroll
            for (int mi = 0; mi < 4; mi++)
                #pragma unroll
                for (int ni = 0; ni < 8; ni++)
                    mma1688(acc[mi][ni], a[mi], b[ni]);
        }
        __syncthreads();
    }

    // epilogue
    int rbase = blockIdx.x * 128 + wm * 64 + (lane >> 2);
    int cbase = nb0 * 8 + wn * 64 + (lane & 3) * 2;
    #pragma unroll
    for (int mi = 0; mi < 4; mi++) {
        #pragma unroll
        for (int half = 0; half < 2; half++) {
            int row = rbase + mi * 16 + half * 8;
            if (row < M) {
                #pragma unroll
                for (int ni = 0; ni < 8; ni++) {
                    int col = cbase + ni * 8;
                    float sc = (col < scale_cols) ? scale : 1.f;
                    float2 o;
                    o.x = (acc[mi][ni][half * 2 + 0] + bias[col])     * sc;
                    o.y = (acc[mi][ni][half * 2 + 1] + bias[col + 1]) * sc;
                    *(float2*)(C + (size_t)row * ldc + col) = o;
                }
            }
        }
    }
}

// ---------------- CSR build ---------------------------------------------------
__global__ void zero_counts() {
    int i = blockIdx.x * blockDim.x + threadIdx.x;
    if (i < NN) { g_deg[i] = 0; g_fill[i] = 0; }
}
__global__ void count_deg(const int* __restrict__ rows) {
    int i = blockIdx.x * blockDim.x + threadIdx.x;
    if (i < NE) atomicAdd(&g_deg[rows[i]], 1);
}
__global__ __launch_bounds__(1024) void scan_deg() {
    __shared__ int warp_sums[32];
    __shared__ int carry;
    int tid = threadIdx.x;
    int lane = tid & 31, w = tid >> 5;
    if (tid == 0) carry = 0;
    __syncthreads();
    for (int base = 0; base < NN; base += 1024) {
        int i = base + tid;
        int v = (i < NN) ? g_deg[i] : 0;
        int x = v;
        #pragma unroll
        for (int d = 1; d < 32; d <<= 1) {
            int y = __shfl_up_sync(0xffffffffu, x, d);
            if (lane >= d) x += y;
        }
        if (lane == 31) warp_sums[w] = x;
        __syncthreads();
        if (w == 0) {
            int s = warp_sums[lane];
            #pragma unroll
            for (int d = 1; d < 32; d <<= 1) {
                int y = __shfl_up_sync(0xffffffffu, s, d);
                if (lane >= d) s += y;
            }
            warp_sums[lane] = s;
        }
        __syncthreads();
        int excl = x - v + carry + (w ? warp_sums[w - 1] : 0);
        if (i < NN) g_off[i] = excl;
        int blocktotal = warp_sums[31];
        __syncthreads();
        if (tid == 0) carry += blocktotal;
        __syncthreads();
    }
    if (tid == 0) g_off[NN] = carry;
}
__global__ void scatter_edges(const int* __restrict__ rows) {
    int i = blockIdx.x * blockDim.x + threadIdx.x;
    if (i < NE) {
        int r = rows[i];
        int pos = g_off[r] + atomicAdd(&g_fill[r], 1);
        g_perm[pos] = i;
    }
}
__global__ void sort_perm() {
    int r = blockIdx.x * blockDim.x + threadIdx.x;
    if (r >= NN) return;
    int b = g_off[r], e = g_off[r + 1];
    for (int i = b + 1; i < e; i++) {
        int key = g_perm[i];
        int j = i - 1;
        while (j >= b && g_perm[j] > key) { g_perm[j + 1] = g_perm[j]; j--; }
        g_perm[j + 1] = key;
    }
}

// ------- SDDMM in perm order (consecutive warps share q row -> L1 hit) -------
__global__ __launch_bounds__(256) void sddmm(
    const int* __restrict__ rows, const int* __restrict__ cols)
{
    int t = (blockIdx.x * blockDim.x + threadIdx.x) >> 5;
    if (t >= NE) return;
    int lane = threadIdx.x & 31;
    int e = g_perm[t];
    int r = __ldg(&rows[e]);
    int c = __ldg(&cols[e]);
    const float4* q4 = reinterpret_cast<const float4*>(g_qkv + (size_t)r * NQKV);
    const float4* k4 = reinterpret_cast<const float4*>(g_qkv + (size_t)c * NQKV + 256);
    float4 qa = q4[lane], qb = q4[lane + 32];
    float4 ka = k4[lane], kb = k4[lane + 32];
    float4 acc;
    acc.x = qa.x * ka.x + qb.x * kb.x;
    acc.y = qa.y * ka.y + qb.y * kb.y;
    acc.z = qa.z * ka.z + qb.z * kb.z;
    acc.w = qa.w * ka.w + qb.w * kb.w;
    #pragma unroll
    for (int m = 2; m <= 16; m <<= 1) {
        acc.x += __shfl_xor_sync(0xffffffffu, acc.x, m);
        acc.y += __shfl_xor_sync(0xffffffffu, acc.y, m);
        acc.z += __shfl_xor_sync(0xffffffffu, acc.z, m);
        acc.w += __shfl_xor_sync(0xffffffffu, acc.w, m);
    }
    if (lane < 2)
        *(float4*)(g_s + (size_t)e * 8 + lane * 4) = acc;
}

// --- per-row softmax + SPMM (warp/row); writes tf32-rounded FRAGMENT layout --
__global__ __launch_bounds__(256) void softmax_spmm(const int* __restrict__ cols)
{
    int row = (blockIdx.x * blockDim.x + threadIdx.x) >> 5;
    if (row >= NN) return;
    int lane = threadIdx.x & 31;
    int beg = g_off[row], end = g_off[row + 1];
    int sub = lane >> 3;       // 4-way edge parallelism
    int hh  = lane & 7;        // head

    float m = -1e30f;
    for (int t = beg + sub; t < end; t += 4)
        m = fmaxf(m, g_s[(size_t)g_perm[t] * 8 + hh]);
    m = fmaxf(m, __shfl_xor_sync(0xffffffffu, m, 8));
    m = fmaxf(m, __shfl_xor_sync(0xffffffffu, m, 16));

    float z = 0.f;
    for (int t = beg + sub; t < end; t += 4)
        z += __expf(g_s[(size_t)g_perm[t] * 8 + hh] - m);
    z += __shfl_xor_sync(0xffffffffu, z, 8);
    z += __shfl_xor_sync(0xffffffffu, z, 16);
    float inv_z = (end > beg) ? (1.f / z) : 0.f;

    float acc[8];
    #pragma unroll
    for (int j = 0; j < 8; j++) acc[j] = 0.f;

    for (int t = beg; t < end; t++) {
        int e = g_perm[t];
        int c = __ldg(&cols[e]);
        float p = __expf(g_s[(size_t)e * 8 + hh] - m) * inv_z;
        const float* vr = g_qkv + (size_t)c * NQKV + 512;
        #pragma unroll
        for (int j = 0; j < 8; j++)
            acc[j] += p * vr[lane + 32 * j];
    }
    #pragma unroll
    for (int j = 0; j < 8; j++) {
        int c = lane + 32 * j;
        g_of[frag_a_idx(row, c)] = f2tf32(acc[j]);
    }
}

// ---------------- launch -----------------------------------------------------
extern "C" void kernel_launch(void* const* d_in, const int* in_sizes, int n_in,
                              void* d_out, int out_size)
{
    const float* h  = (const float*)d_in[0];
    const float* Wq = (const float*)d_in[1];
    const float* bq = (const float*)d_in[2];
    const float* Wk = (const float*)d_in[3];
    const float* bk = (const float*)d_in[4];
    const float* Wv = (const float*)d_in[5];
    const float* bv = (const float*)d_in[6];
    const float* Wo = (const float*)d_in[7];
    const float* bo = (const float*)d_in[8];
    const int* rows = (const int*)d_in[9];
    const int* cols = (const int*)d_in[10];
    float* out = (float*)d_out;

    void *paf, *pof, *pwf, *pbias, *pqkv;
    cudaGetSymbolAddress(&paf, g_af);
    cudaGetSymbolAddress(&pof, g_of);
    cudaGetSymbolAddress(&pwf, g_wf);
    cudaGetSymbolAddress(&pbias, g_bias);
    cudaGetSymbolAddress(&pqkv, g_qkv);
    float* wf = (float*)pwf;

    cudaFuncSetAttribute(gemm_mma, cudaFuncAttributeMaxDynamicSharedMemorySize, SMEM_GEMM);

    const float scaling = 0.17677669529663687f;  // 32^-0.5

    // 1-4: prep + CSR zero (so launch #5 = gemm_qkv for ncu)
    prep_a<<<(NN * HID + 255) / 256, 256>>>(h);
    prep_wqkv<<<(3 * HID * HID + 255) / 256, 256>>>(Wq, Wk, Wv, bq, bk, bv);
    prep_wo<<<(HID * HID + 255) / 256, 256>>>(Wo);
    zero_counts<<<(NN + 255) / 256, 256>>>();

    // 5: fused QKV GEMM (N = 768)
    dim3 gQ((NN + 127) / 128, 3);
    gemm_mma<<<gQ, 256, SMEM_GEMM>>>((const float*)paf, wf, (const float*)pbias,
                                     (float*)pqkv, NN, NQKV, scaling, 256);

    // 6-9: CSR build
    count_deg<<<(NE + 255) / 256, 256>>>(rows);
    scan_deg<<<1, 1024>>>();
    scatter_edges<<<(NE + 255) / 256, 256>>>(rows);
    sort_perm<<<(NN + 255) / 256, 256>>>();

    // 10-11: edge kernels
    sddmm<<<(NE * 32 + 255) / 256, 256>>>(rows, cols);
    softmax_spmm<<<(NN * 32 + 255) / 256, 256>>>(cols);

    // 12: output GEMM (N = 256)
    dim3 gO((NN + 127) / 128, 1);
    gemm_mma<<<gO, 256, SMEM_GEMM>>>((const float*)pof, wf + 196608, bo,
                                     out, NN, HID, 1.f, 0);
}

// round 13
// speedup vs baseline: 1.8754x; 1.0592x over previous
#include <cuda_runtime.h>
#include <cuda_bf16.h>
#include <cstdint>

#define NN 20000
#define NE 320000
#define HID 256
#define NQKV 768
#define NHEADS 8
#define MB_TOT 1256          // 157*8 row-blocks of 16 (padded)
#define MAXE 96              // smem-cached edges per row (Poisson(16): overflow ~0)

// ---------------- scratch (static device globals; no allocation) -------------
__device__ float g_af [(size_t)MB_TOT * 32 * 128];  // A fragments (tf32 h)
__device__ float g_of [(size_t)MB_TOT * 32 * 128];  // attention-out fragments
__device__ float g_wf [262144];                     // Wqkv frags + Wo frags
__device__ float g_bias[NQKV];                      // concat bq|bk|bv
__device__ float g_qkv[(size_t)NN * NQKV];          // q|k|v rows
__device__ float g_s  [(size_t)NE * NHEADS];        // overflow score spill
__device__ int   g_deg[NN];
__device__ int   g_off[NN + 1];
__device__ int   g_fill[NN];
__device__ int   g_perm[NE];

// ---------------- helpers ----------------------------------------------------
__device__ __forceinline__ uint32_t smem_u32(const void* p) {
    uint32_t a;
    asm("{ .reg .u64 t; cvta.to.shared.u64 t, %1; cvt.u32.u64 %0, t; }" : "=r"(a) : "l"(p));
    return a;
}
__device__ __forceinline__ float f2tf32(float a) {
    uint32_t u; asm("cvt.rna.tf32.f32 %0, %1;" : "=r"(u) : "f"(a));
    return __uint_as_float(u);
}
__device__ __forceinline__ size_t frag_a_idx(int row, int c) {
    return ((size_t)(row >> 4) * 32 + (c >> 3)) * 128 +
           ((row & 7) * 4 + (c & 3)) * 4 + ((row >> 3) & 1) + 2 * ((c >> 2) & 1);
}
__device__ __forceinline__ size_t frag_b_idx(int k, int n) {
    return ((size_t)(n >> 3) * 32 + (k >> 3)) * 64 +
           ((n & 7) * 4 + (k & 3)) * 2 + ((k >> 2) & 1);
}
__device__ __forceinline__ void cp_async16(uint32_t dst, const float* src) {
    asm volatile("cp.async.cg.shared.global [%0], [%1], 16;" :: "r"(dst), "l"(src) : "memory");
}
__device__ __forceinline__ void mma1688(float* d, const float4& a, const float2& b) {
    asm volatile(
        "mma.sync.aligned.m16n8k8.row.col.f32.tf32.tf32.f32 "
        "{%0,%1,%2,%3}, {%4,%5,%6,%7}, {%8,%9}, {%0,%1,%2,%3};"
        : "+f"(d[0]), "+f"(d[1]), "+f"(d[2]), "+f"(d[3])
        : "r"(__float_as_uint(a.x)), "r"(__float_as_uint(a.y)),
          "r"(__float_as_uint(a.z)), "r"(__float_as_uint(a.w)),
          "r"(__float_as_uint(b.x)), "r"(__float_as_uint(b.y)));
}

// ---------------- prep: tf32 round + fragment swizzle ------------------------
__global__ void prep_a(const float* __restrict__ h) {
    int i = blockIdx.x * blockDim.x + threadIdx.x;
    if (i >= NN * HID) return;
    int row = i >> 8, c = i & 255;
    g_af[frag_a_idx(row, c)] = f2tf32(h[i]);
}
__global__ void prep_wqkv(const float* __restrict__ Wq, const float* __restrict__ Wk,
                          const float* __restrict__ Wv, const float* __restrict__ bq,
                          const float* __restrict__ bk, const float* __restrict__ bv) {
    int i = blockIdx.x * blockDim.x + threadIdx.x;
    if (i < NQKV)
        g_bias[i] = (i < 256) ? bq[i] : (i < 512) ? bk[i - 256] : bv[i - 512];
    if (i >= 3 * HID * HID) return;
    int which = i >> 16, rem = i & 65535;
    int k = rem >> 8, n = rem & 255;
    const float* W = (which == 0) ? Wq : (which == 1) ? Wk : Wv;
    g_wf[frag_b_idx(k, which * 256 + n)] = f2tf32(W[rem]);
}
__global__ void prep_wo(const float* __restrict__ Wo) {
    int i = blockIdx.x * blockDim.x + threadIdx.x;
    if (i >= HID * HID) return;
    int k = i >> 8, n = i & 255;
    g_wf[196608 + frag_b_idx(k, n)] = f2tf32(Wo[i]);
}

// ---------------- tf32 mma.sync GEMM: C = (A @ W + bias) * colscale ----------
#define SMEM_GEMM 98304

__device__ __forceinline__ void load_stage(
    uint32_t da, uint32_t db, int c, const float* __restrict__ Af,
    const float* __restrict__ Bf, int mb0, int nb0, int tid)
{
    #pragma unroll
    for (int i = 0; i < 4; i++) {      // A: 1024 x 16B
        int idx = tid + i * 256;
        int mbL = idx >> 7, kbL = (idx >> 5) & 3, l = idx & 31;
        const float* src = Af + ((size_t)(mb0 + mbL) * 32 + c * 4 + kbL) * 128 + l * 4;
        cp_async16(da + idx * 16, src);
    }
    #pragma unroll
    for (int i = 0; i < 8; i++) {      // B: 2048 x 16B
        int idx = tid + i * 256;
        int nbL = idx >> 6, kbL = (idx >> 4) & 3, part = idx & 15;
        const float* src = Bf + ((size_t)(nb0 + nbL) * 32 + c * 4 + kbL) * 64 + part * 4;
        cp_async16(db + idx * 16, src);
    }
    asm volatile("cp.async.commit_group;" ::: "memory");
}

__global__ void __launch_bounds__(256) gemm_mma(
    const float* __restrict__ Af, const float* __restrict__ Bf,
    const float* __restrict__ bias, float* __restrict__ C, int M, int ldc,
    float scale, int scale_cols)
{
    extern __shared__ float sm[];
    float* sA[2] = { sm,         sm + 4096 };
    float* sB[2] = { sm + 8192,  sm + 16384 };

    int tid = threadIdx.x, wid = tid >> 5, lane = tid & 31;
    int wm = wid >> 2, wn = wid & 3;
    int mb0 = blockIdx.x * 8;
    int nb0 = blockIdx.y * 32;

    float acc[4][8][4];
    #pragma unroll
    for (int a = 0; a < 4; a++)
        #pragma unroll
        for (int b = 0; b < 8; b++)
            #pragma unroll
            for (int r = 0; r < 4; r++) acc[a][b][r] = 0.f;

    uint32_t uA[2] = { smem_u32(sA[0]), smem_u32(sA[1]) };
    uint32_t uB[2] = { smem_u32(sB[0]), smem_u32(sB[1]) };

    load_stage(uA[0], uB[0], 0, Af, Bf, mb0, nb0, tid);

    #pragma unroll
    for (int c = 0; c < 8; c++) {
        if (c < 7) {
            load_stage(uA[(c + 1) & 1], uB[(c + 1) & 1], c + 1, Af, Bf, mb0, nb0, tid);
            asm volatile("cp.async.wait_group 1;" ::: "memory");
        } else {
            asm volatile("cp.async.wait_group 0;" ::: "memory");
        }
        __syncthreads();
        const float* cA = sA[c & 1];
        const float* cB = sB[c & 1];
        #pragma unroll
        for (int s = 0; s < 4; s++) {
            float4 a[4];
            float2 b[8];
            #pragma unroll
            for (int mi = 0; mi < 4; mi++)
                a[mi] = *(const float4*)(cA + ((wm * 4 + mi) * 4 + s) * 128 + lane * 4);
            #pragma unroll
            for (int ni = 0; ni < 8; ni++)
                b[ni] = *(const float2*)(cB + ((wn * 8 + ni) * 4 + s) * 64 + lane * 2);
            #pragma unroll
            for (int mi = 0; mi < 4; mi++)
                #pragma unroll
                for (int ni = 0; ni < 8; ni++)
                    mma1688(acc[mi][ni], a[mi], b[ni]);
        }
        __syncthreads();
    }

    int rbase = blockIdx.x * 128 + wm * 64 + (lane >> 2);
    int cbase = nb0 * 8 + wn * 64 + (lane & 3) * 2;
    #pragma unroll
    for (int mi = 0; mi < 4; mi++) {
        #pragma unroll
        for (int half = 0; half < 2; half++) {
            int row = rbase + mi * 16 + half * 8;
            if (row < M) {
                #pragma unroll
                for (int ni = 0; ni < 8; ni++) {
                    int col = cbase + ni * 8;
                    float sc = (col < scale_cols) ? scale : 1.f;
                    float2 o;
                    o.x = (acc[mi][ni][half * 2 + 0] + bias[col])     * sc;
                    o.y = (acc[mi][ni][half * 2 + 1] + bias[col + 1]) * sc;
                    *(float2*)(C + (size_t)row * ldc + col) = o;
                }
            }
        }
    }
}

// ---------------- CSR build ---------------------------------------------------
__global__ void count_deg(const int* __restrict__ rows) {
    int i = blockIdx.x * blockDim.x + threadIdx.x;
    if (i < NE) atomicAdd(&g_deg[rows[i]], 1);
}
__global__ __launch_bounds__(1024) void scan_deg() {
    __shared__ int warp_sums[32];
    __shared__ int carry;
    int tid = threadIdx.x;
    int lane = tid & 31, w = tid >> 5;
    if (tid == 0) carry = 0;
    __syncthreads();
    for (int base = 0; base < NN; base += 1024) {
        int i = base + tid;
        int v = (i < NN) ? g_deg[i] : 0;
        int x = v;
        #pragma unroll
        for (int d = 1; d < 32; d <<= 1) {
            int y = __shfl_up_sync(0xffffffffu, x, d);
            if (lane >= d) x += y;
        }
        if (lane == 31) warp_sums[w] = x;
        __syncthreads();
        if (w == 0) {
            int s = warp_sums[lane];
            #pragma unroll
            for (int d = 1; d < 32; d <<= 1) {
                int y = __shfl_up_sync(0xffffffffu, s, d);
                if (lane >= d) s += y;
            }
            warp_sums[lane] = s;
        }
        __syncthreads();
        int excl = x - v + carry + (w ? warp_sums[w - 1] : 0);
        if (i < NN) g_off[i] = excl;
        int blocktotal = warp_sums[31];
        __syncthreads();
        if (tid == 0) carry += blocktotal;
        __syncthreads();
    }
    if (tid == 0) g_off[NN] = carry;
}
__global__ void scatter_edges(const int* __restrict__ rows) {
    int i = blockIdx.x * blockDim.x + threadIdx.x;
    if (i < NE) {
        int r = rows[i];
        int pos = g_off[r] + atomicAdd(&g_fill[r], 1);
        g_perm[pos] = i;
    }
}
// deterministic per-row order; sort in registers (L1) not global RMW chains
__global__ void sort_perm() {
    int r = blockIdx.x * blockDim.x + threadIdx.x;
    if (r >= NN) return;
    int b = g_off[r], e = g_off[r + 1];
    int n = e - b;
    if (n <= 1) return;
    if (n <= MAXE) {
        int loc[MAXE];
        for (int i = 0; i < n; i++) loc[i] = g_perm[b + i];
        for (int i = 1; i < n; i++) {
            int key = loc[i], j = i - 1;
            while (j >= 0 && loc[j] > key) { loc[j + 1] = loc[j]; j--; }
            loc[j + 1] = key;
        }
        for (int i = 0; i < n; i++) g_perm[b + i] = loc[i];
    } else {
        for (int i = b + 1; i < e; i++) {
            int key = g_perm[i], j = i - 1;
            while (j >= b && g_perm[j] > key) { g_perm[j + 1] = g_perm[j]; j--; }
            g_perm[j + 1] = key;
        }
    }
}

// ------ fused SDDMM + softmax + SPMM: one warp per row -----------------------
// head of flat col c is c&7, so lane-partition {lane, lane+32, ...} keeps all
// partials of one head (lane&7) in one lane; xor-8/16 reduces over the group.
__global__ __launch_bounds__(256) void edge_fused(const int* __restrict__ cols)
{
    __shared__ float sp[8][MAXE][8];   // [warp][edge][head] scores -> probs
    int w = threadIdx.x >> 5, lane = threadIdx.x & 31;
    int row = blockIdx.x * 8 + w;
    if (row >= NN) return;
    int beg = g_off[row], deg = g_off[row + 1] - beg;
    int hh = lane & 7, sub = lane >> 3;

    const float* qrp = g_qkv + (size_t)row * NQKV;
    float qr[8];
    #pragma unroll
    for (int j = 0; j < 8; j++) qr[j] = qrp[lane + 32 * j];

    // phase 1: scores
    for (int t = 0; t < deg; t++) {
        int e = g_perm[beg + t];
        int c = __ldg(&cols[e]);
        const float* kr = g_qkv + (size_t)c * NQKV + 256;
        float acc = 0.f;
        #pragma unroll
        for (int j = 0; j < 8; j++) acc += qr[j] * kr[lane + 32 * j];
        acc += __shfl_xor_sync(0xffffffffu, acc, 8);
        acc += __shfl_xor_sync(0xffffffffu, acc, 16);
        if (lane < 8) {
            if (t < MAXE) sp[w][t][lane] = acc;
            else          g_s[(size_t)e * 8 + lane] = acc;
        }
    }
    __syncwarp();

    // softmax stats (4 edge-subsets x 8 heads)
    float m = -1e30f;
    for (int t = sub; t < deg; t += 4) {
        float s = (t < MAXE) ? sp[w][t][hh] : g_s[(size_t)g_perm[beg + t] * 8 + hh];
        m = fmaxf(m, s);
    }
    m = fmaxf(m, __shfl_xor_sync(0xffffffffu, m, 8));
    m = fmaxf(m, __shfl_xor_sync(0xffffffffu, m, 16));
    float z = 0.f;
    for (int t = sub; t < deg; t += 4) {
        float s = (t < MAXE) ? sp[w][t][hh] : g_s[(size_t)g_perm[beg + t] * 8 + hh];
        z += __expf(s - m);
    }
    z += __shfl_xor_sync(0xffffffffu, z, 8);
    z += __shfl_xor_sync(0xffffffffu, z, 16);
    float invz = deg ? (1.f / z) : 0.f;
    __syncwarp();

    // normalize in-place (probabilities computed once)
    for (int t = sub; t < deg && t < MAXE; t += 4)
        sp[w][t][hh] = __expf(sp[w][t][hh] - m) * invz;
    __syncwarp();

    // phase 2: SPMM
    float acc[8];
    #pragma unroll
    for (int j = 0; j < 8; j++) acc[j] = 0.f;
    for (int t = 0; t < deg; t++) {
        int e = g_perm[beg + t];
        int c = __ldg(&cols[e]);
        float p = (t < MAXE) ? sp[w][t][hh]
                             : __expf(g_s[(size_t)e * 8 + hh] - m) * invz;
        const float* vr = g_qkv + (size_t)c * NQKV + 512;
        #pragma unroll
        for (int j = 0; j < 8; j++) acc[j] += p * vr[lane + 32 * j];
    }
    #pragma unroll
    for (int j = 0; j < 8; j++)
        g_of[frag_a_idx(row, lane + 32 * j)] = f2tf32(acc[j]);
}

// ---------------- launch -----------------------------------------------------
extern "C" void kernel_launch(void* const* d_in, const int* in_sizes, int n_in,
                              void* d_out, int out_size)
{
    const float* h  = (const float*)d_in[0];
    const float* Wq = (const float*)d_in[1];
    const float* bq = (const float*)d_in[2];
    const float* Wk = (const float*)d_in[3];
    const float* bk = (const float*)d_in[4];
    const float* Wv = (const float*)d_in[5];
    const float* bv = (const float*)d_in[6];
    const float* Wo = (const float*)d_in[7];
    const float* bo = (const float*)d_in[8];
    const int* rows = (const int*)d_in[9];
    const int* cols = (const int*)d_in[10];
    float* out = (float*)d_out;

    void *paf, *pof, *pwf, *pbias, *pqkv, *pdeg, *pfill;
    cudaGetSymbolAddress(&paf, g_af);
    cudaGetSymbolAddress(&pof, g_of);
    cudaGetSymbolAddress(&pwf, g_wf);
    cudaGetSymbolAddress(&pbias, g_bias);
    cudaGetSymbolAddress(&pqkv, g_qkv);
    cudaGetSymbolAddress(&pdeg, g_deg);
    cudaGetSymbolAddress(&pfill, g_fill);
    float* wf = (float*)pwf;

    cudaFuncSetAttribute(gemm_mma, cudaFuncAttributeMaxDynamicSharedMemorySize, SMEM_GEMM);

    const float scaling = 0.17677669529663687f;  // 32^-0.5

    // counters zeroed via async memset (not a kernel launch)
    cudaMemsetAsync(pdeg, 0, NN * sizeof(int));
    cudaMemsetAsync(pfill, 0, NN * sizeof(int));

    // 1-3: prep
    prep_a<<<(NN * HID + 255) / 256, 256>>>(h);
    prep_wqkv<<<(3 * HID * HID + 255) / 256, 256>>>(Wq, Wk, Wv, bq, bk, bv);
    prep_wo<<<(HID * HID + 255) / 256, 256>>>(Wo);

    // 4: fused QKV GEMM (slot 4 for ncu)
    dim3 gQ((NN + 127) / 128, 3);
    gemm_mma<<<gQ, 256, SMEM_GEMM>>>((const float*)paf, wf, (const float*)pbias,
                                     (float*)pqkv, NN, NQKV, scaling, 256);

    // 5-8: CSR build
    count_deg<<<(NE + 255) / 256, 256>>>(rows);
    scan_deg<<<1, 1024>>>();
    scatter_edges<<<(NE + 255) / 256, 256>>>(rows);
    sort_perm<<<(NN + 255) / 256, 256>>>();

    // 9: fused edge phase
    edge_fused<<<(NN + 7) / 8, 256>>>(cols);

    // 10: output GEMM
    dim3 gO((NN + 127) / 128, 1);
    gemm_mma<<<gO, 256, SMEM_GEMM>>>((const float*)pof, wf + 196608, bo,
                                     out, NN, HID, 1.f, 0);
}